// round 2
// baseline (speedup 1.0000x reference)
#include <cuda_runtime.h>
#include <cuda_bf16.h>
#include <math.h>

#define MAXV    2000000
#define NMESH   4

// Scratch: Lx (3 comps) + row_sum packed as float4 per row. 32 MB.
// Zero-initialized at module load; finalize_kernel restores zeros every call.
__device__ float4 d_acc[MAXV];
// Padded gather table: (x, y, z, 0) so gathers are a single LDG.128.
__device__ float4 d_verts4[MAXV];
__device__ float  d_inv_nvpm[NMESH];

// ---------------------------------------------------------------------------
// Kernel 1: build padded verts table + zero output scalar
// ---------------------------------------------------------------------------
__global__ void prep_kernel(const float* __restrict__ verts,
                            float* __restrict__ out, int v) {
    int stride = gridDim.x * blockDim.x;
    for (int i = blockIdx.x * blockDim.x + threadIdx.x; i < v; i += stride) {
        const float* p = verts + 3 * (long long)i;
        float4 q;
        q.x = __ldg(p + 0);
        q.y = __ldg(p + 1);
        q.z = __ldg(p + 2);
        q.w = 0.f;
        d_verts4[i] = q;
    }
    if (blockIdx.x == 0 && threadIdx.x == 0)
        out[0] = 0.f;
}

// ---------------------------------------------------------------------------
// Kernel 2: mesh vertex counts via binary search (verts_mesh_idx is sorted)
// ---------------------------------------------------------------------------
__global__ void mesh_count_kernel(const int* __restrict__ idx, int v) {
    int m = threadIdx.x;
    if (m >= NMESH) return;
    auto lb = [&](int val) {
        int lo = 0, hi = v;
        while (lo < hi) {
            int mid = (lo + hi) >> 1;
            if (__ldg(idx + mid) < val) lo = mid + 1; else hi = mid;
        }
        return lo;
    };
    int s = lb(m);
    int e = lb(m + 1);
    int cnt = e - s;
    d_inv_nvpm[m] = (cnt > 0) ? (1.f / (float)cnt) : 0.f;
}

// ---------------------------------------------------------------------------
// Kernel 3: COO scatter.  One thread handles 4 nnz. Streams use evict-first
// (__ldcs) so they don't displace verts4/acc from L2. Gather is one LDG.128.
// Each nnz contributes one red.global.add.v4.f32.
// ---------------------------------------------------------------------------
__device__ __forceinline__ void red_add_v4(float4* addr, float x, float y,
                                           float z, float w) {
    asm volatile("red.global.add.v4.f32 [%0], {%1, %2, %3, %4};"
                 :: "l"(addr), "f"(x), "f"(y), "f"(z), "f"(w)
                 : "memory");
}

__device__ __forceinline__ void scatter_one(float v, int r, int c) {
    float4 p = __ldg(&d_verts4[c]);
    red_add_v4(&d_acc[r], v * p.x, v * p.y, v * p.z, v);
}

__global__ void scatter_kernel(const float* __restrict__ vals,
                               const int*   __restrict__ rows,
                               const int*   __restrict__ cols,
                               int nnz) {
    int t = blockIdx.x * blockDim.x + threadIdx.x;
    int base = t * 4;
    if (base + 3 < nnz) {
        float4 v = __ldcs(reinterpret_cast<const float4*>(vals + base));
        int4   r = __ldcs(reinterpret_cast<const int4*>(rows + base));
        int4   c = __ldcs(reinterpret_cast<const int4*>(cols + base));
        // Issue all four gathers before the REDs (ILP for L2 latency).
        float4 p0 = __ldg(&d_verts4[c.x]);
        float4 p1 = __ldg(&d_verts4[c.y]);
        float4 p2 = __ldg(&d_verts4[c.z]);
        float4 p3 = __ldg(&d_verts4[c.w]);
        red_add_v4(&d_acc[r.x], v.x * p0.x, v.x * p0.y, v.x * p0.z, v.x);
        red_add_v4(&d_acc[r.y], v.y * p1.x, v.y * p1.y, v.y * p1.z, v.y);
        red_add_v4(&d_acc[r.z], v.z * p2.x, v.z * p2.y, v.z * p2.z, v.z);
        red_add_v4(&d_acc[r.w], v.w * p3.x, v.w * p3.y, v.w * p3.z, v.w);
    } else {
        for (int i = base; i < nnz; i++)
            scatter_one(__ldg(vals + i), __ldg(rows + i), __ldg(cols + i));
    }
}

// ---------------------------------------------------------------------------
// Kernel 4: per-vertex loss + global reduction; restores d_acc to zeros.
// ---------------------------------------------------------------------------
__global__ void finalize_kernel(const int*   __restrict__ mesh_idx,
                                const float* __restrict__ coefs,
                                float* __restrict__ out,
                                int v) {
    int i = blockIdx.x * blockDim.x + threadIdx.x;
    float acc = 0.f;
    if (i < v) {
        float4 L = d_acc[i];
        d_acc[i] = make_float4(0.f, 0.f, 0.f, 0.f);   // restore zeros for next call
        float rs = L.w;
        float nw = (rs > 0.f) ? (1.f / rs) : rs;
        float4 p = d_verts4[i];
        float rx = L.x * nw - p.x;
        float ry = L.y * nw - p.y;
        float rz = L.z * nw - p.z;
        float loss = sqrtf(rx * rx + ry * ry + rz * rz);
        float w = d_inv_nvpm[__ldg(mesh_idx + i)];
        acc = loss * w * __ldg(coefs + i) * (1.f / (float)NMESH);
    }

    // warp reduce
    #pragma unroll
    for (int off = 16; off > 0; off >>= 1)
        acc += __shfl_down_sync(0xFFFFFFFFu, acc, off);

    __shared__ float sdata[32];
    int lane = threadIdx.x & 31;
    int wid  = threadIdx.x >> 5;
    if (lane == 0) sdata[wid] = acc;
    __syncthreads();

    int nwarps = blockDim.x >> 5;
    if (wid == 0) {
        acc = (lane < nwarps) ? sdata[lane] : 0.f;
        #pragma unroll
        for (int off = 16; off > 0; off >>= 1)
            acc += __shfl_down_sync(0xFFFFFFFFu, acc, off);
        if (lane == 0)
            atomicAdd(out, acc);
    }
}

// ---------------------------------------------------------------------------
// Launch
// ---------------------------------------------------------------------------
extern "C" void kernel_launch(void* const* d_in, const int* in_sizes, int n_in,
                              void* d_out, int out_size) {
    const float* verts    = (const float*)d_in[0];
    const float* lap_vals = (const float*)d_in[1];
    const int*   lap_rows = (const int*)  d_in[2];
    const int*   lap_cols = (const int*)  d_in[3];
    const int*   mesh_idx = (const int*)  d_in[4];
    const float* coefs    = (const float*)d_in[5];
    float*       out      = (float*)d_out;

    int nnz = in_sizes[1];
    int v   = in_sizes[4];

    // 1. build padded verts table + zero output
    {
        int threads = 256;
        int blocks = (v + threads - 1) / threads;
        if (blocks > 8192) blocks = 8192;
        prep_kernel<<<blocks, threads>>>(verts, out, v);
    }

    // 2. mesh counts (tiny)
    mesh_count_kernel<<<1, 32>>>(mesh_idx, v);

    // 3. scatter
    {
        int threads = 256;
        int quads = (nnz + 3) / 4;
        int blocks = (quads + threads - 1) / threads;
        scatter_kernel<<<blocks, threads>>>(lap_vals, lap_rows, lap_cols, nnz);
    }

    // 4. finalize + reduce (+ restore zeros)
    {
        int threads = 256;
        int blocks = (v + threads - 1) / threads;
        finalize_kernel<<<blocks, threads>>>(mesh_idx, coefs, out, v);
    }
}

// round 3
// speedup vs baseline: 1.3073x; 1.3073x over previous
#include <cuda_runtime.h>
#include <cuda_bf16.h>
#include <math.h>

#define MAXV    2000000
#define NMESH   4

// Scratch: Lx (3 comps) + row_sum packed as float4 per row. 32 MB.
__device__ float4 d_acc[MAXV];
// Padded gather table: (x, y, z, 0) so gathers are a single LDG.128.
__device__ float4 d_verts4[MAXV];
__device__ float  d_inv_nvpm[NMESH];

// ---------------------------------------------------------------------------
// Kernel 1: build padded verts table, zero accumulator, zero output scalar.
// Pure streaming stores (no load+store to same line).
// ---------------------------------------------------------------------------
__global__ void prep_kernel(const float* __restrict__ verts,
                            float* __restrict__ out, int v) {
    const float4 z = make_float4(0.f, 0.f, 0.f, 0.f);
    int stride = gridDim.x * blockDim.x;
    for (int i = blockIdx.x * blockDim.x + threadIdx.x; i < v; i += stride) {
        const float* p = verts + 3 * (long long)i;
        float4 q;
        q.x = __ldg(p + 0);
        q.y = __ldg(p + 1);
        q.z = __ldg(p + 2);
        q.w = 0.f;
        d_verts4[i] = q;
        d_acc[i] = z;
    }
    if (blockIdx.x == 0 && threadIdx.x == 0)
        out[0] = 0.f;
}

// ---------------------------------------------------------------------------
// Kernel 2: mesh vertex counts via binary search (verts_mesh_idx is sorted)
// ---------------------------------------------------------------------------
__global__ void mesh_count_kernel(const int* __restrict__ idx, int v) {
    int m = threadIdx.x;
    if (m >= NMESH) return;
    auto lb = [&](int val) {
        int lo = 0, hi = v;
        while (lo < hi) {
            int mid = (lo + hi) >> 1;
            if (__ldg(idx + mid) < val) lo = mid + 1; else hi = mid;
        }
        return lo;
    };
    int s = lb(m);
    int e = lb(m + 1);
    int cnt = e - s;
    d_inv_nvpm[m] = (cnt > 0) ? (1.f / (float)cnt) : 0.f;
}

// ---------------------------------------------------------------------------
// Kernel 3: COO scatter.  One thread handles 4 nnz. Streams use evict-first
// (__ldcs) so they don't displace verts4/acc from L2. Gather is one LDG.128.
// Each nnz contributes one red.global.add.v4.f32.
// ---------------------------------------------------------------------------
__device__ __forceinline__ void red_add_v4(float4* addr, float x, float y,
                                           float z, float w) {
    asm volatile("red.global.add.v4.f32 [%0], {%1, %2, %3, %4};"
                 :: "l"(addr), "f"(x), "f"(y), "f"(z), "f"(w)
                 : "memory");
}

__device__ __forceinline__ void scatter_one(float v, int r, int c) {
    float4 p = __ldg(&d_verts4[c]);
    red_add_v4(&d_acc[r], v * p.x, v * p.y, v * p.z, v);
}

__global__ void scatter_kernel(const float* __restrict__ vals,
                               const int*   __restrict__ rows,
                               const int*   __restrict__ cols,
                               int nnz) {
    int t = blockIdx.x * blockDim.x + threadIdx.x;
    int base = t * 4;
    if (base + 3 < nnz) {
        float4 v = __ldcs(reinterpret_cast<const float4*>(vals + base));
        int4   r = __ldcs(reinterpret_cast<const int4*>(rows + base));
        int4   c = __ldcs(reinterpret_cast<const int4*>(cols + base));
        // Issue all four gathers before the REDs (ILP for L2 latency).
        float4 p0 = __ldg(&d_verts4[c.x]);
        float4 p1 = __ldg(&d_verts4[c.y]);
        float4 p2 = __ldg(&d_verts4[c.z]);
        float4 p3 = __ldg(&d_verts4[c.w]);
        red_add_v4(&d_acc[r.x], v.x * p0.x, v.x * p0.y, v.x * p0.z, v.x);
        red_add_v4(&d_acc[r.y], v.y * p1.x, v.y * p1.y, v.y * p1.z, v.y);
        red_add_v4(&d_acc[r.z], v.z * p2.x, v.z * p2.y, v.z * p2.z, v.z);
        red_add_v4(&d_acc[r.w], v.w * p3.x, v.w * p3.y, v.w * p3.z, v.w);
    } else {
        for (int i = base; i < nnz; i++)
            scatter_one(__ldg(vals + i), __ldg(rows + i), __ldg(cols + i));
    }
}

// ---------------------------------------------------------------------------
// Kernel 4: per-vertex loss + global reduction (READ-ONLY on d_acc).
// ---------------------------------------------------------------------------
__global__ void finalize_kernel(const int*   __restrict__ mesh_idx,
                                const float* __restrict__ coefs,
                                float* __restrict__ out,
                                int v) {
    int i = blockIdx.x * blockDim.x + threadIdx.x;
    float acc = 0.f;
    if (i < v) {
        float4 L = __ldg(&d_acc[i]);
        float rs = L.w;
        float nw = (rs > 0.f) ? (1.f / rs) : rs;
        float4 p = __ldg(&d_verts4[i]);
        float rx = L.x * nw - p.x;
        float ry = L.y * nw - p.y;
        float rz = L.z * nw - p.z;
        float loss = sqrtf(rx * rx + ry * ry + rz * rz);
        float w = d_inv_nvpm[__ldg(mesh_idx + i)];
        acc = loss * w * __ldg(coefs + i) * (1.f / (float)NMESH);
    }

    // warp reduce
    #pragma unroll
    for (int off = 16; off > 0; off >>= 1)
        acc += __shfl_down_sync(0xFFFFFFFFu, acc, off);

    __shared__ float sdata[32];
    int lane = threadIdx.x & 31;
    int wid  = threadIdx.x >> 5;
    if (lane == 0) sdata[wid] = acc;
    __syncthreads();

    int nwarps = blockDim.x >> 5;
    if (wid == 0) {
        acc = (lane < nwarps) ? sdata[lane] : 0.f;
        #pragma unroll
        for (int off = 16; off > 0; off >>= 1)
            acc += __shfl_down_sync(0xFFFFFFFFu, acc, off);
        if (lane == 0)
            atomicAdd(out, acc);
    }
}

// ---------------------------------------------------------------------------
// Launch
// ---------------------------------------------------------------------------
extern "C" void kernel_launch(void* const* d_in, const int* in_sizes, int n_in,
                              void* d_out, int out_size) {
    const float* verts    = (const float*)d_in[0];
    const float* lap_vals = (const float*)d_in[1];
    const int*   lap_rows = (const int*)  d_in[2];
    const int*   lap_cols = (const int*)  d_in[3];
    const int*   mesh_idx = (const int*)  d_in[4];
    const float* coefs    = (const float*)d_in[5];
    float*       out      = (float*)d_out;

    int nnz = in_sizes[1];
    int v   = in_sizes[4];

    // 1. build padded verts table + zero accumulator + zero output
    {
        int threads = 256;
        int blocks = (v + threads - 1) / threads;
        if (blocks > 8192) blocks = 8192;
        prep_kernel<<<blocks, threads>>>(verts, out, v);
    }

    // 2. mesh counts (tiny)
    mesh_count_kernel<<<1, 32>>>(mesh_idx, v);

    // 3. scatter
    {
        int threads = 256;
        int quads = (nnz + 3) / 4;
        int blocks = (quads + threads - 1) / threads;
        scatter_kernel<<<blocks, threads>>>(lap_vals, lap_rows, lap_cols, nnz);
    }

    // 4. finalize + reduce (read-only)
    {
        int threads = 256;
        int blocks = (v + threads - 1) / threads;
        finalize_kernel<<<blocks, threads>>>(mesh_idx, coefs, out, v);
    }
}